// round 6
// baseline (speedup 1.0000x reference)
#include <cuda_runtime.h>
#include <math.h>

#define H 1536
#define HK 8
#define HV 16
#define DK 64
#define DV 64
#define KEY_DIM 512
#define VALUE_DIM 1024
#define CONV_DIM 2048
#define NROWS (CONV_DIM + VALUE_DIM + 2*HV)   // 3104

// ---- gemv_in tiling: 16 rows/block, 4 chunks of 4 rows ----
#define IN_RPB 16
#define IN_BLOCKS (NROWS / IN_RPB)            // 194
#define IN_ROWB (H * 4)                       // 6144 B per row
#define IN_CHUNKB (4 * IN_ROWB)               // 24576 B
#define IN_SMEM_X 0
#define IN_SMEM_W (H * 4)                     // 6144
#define IN_SMEM_MBAR (IN_SMEM_W + IN_RPB * IN_ROWB)   // 6144 + 98304 = 104448
#define IN_SMEM_TOTAL (IN_SMEM_MBAR + 64)     // 104512

// ---- gemv_out tiling: 16 rows/block, 4 chunks of 4 rows ----
#define OUT_RPB 16
#define OUT_BLOCKS (H / OUT_RPB)              // 96
#define OUT_ROWB (VALUE_DIM * 4)              // 4096 B per row
#define OUT_CHUNKB (4 * OUT_ROWB)             // 16384 B
#define OUT_SMEM_O 0
#define OUT_SMEM_W (VALUE_DIM * 4)            // 4096
#define OUT_SMEM_MBAR (OUT_SMEM_W + OUT_RPB * OUT_ROWB)  // 4096 + 65536 = 69632
#define OUT_SMEM_TOTAL (OUT_SMEM_MBAR + 64)   // 69696

__device__ __align__(16) float g_qkv[CONV_DIM];
__device__ __align__(16) float g_z[VALUE_DIM];
__device__ __align__(16) float g_ab[2*HV];
__device__ __align__(16) float g_outf[VALUE_DIM];

__device__ __forceinline__ float warp_sum(float v) {
#pragma unroll
    for (int o = 16; o > 0; o >>= 1) v += __shfl_xor_sync(0xffffffffu, v, o);
    return v;
}

__device__ __forceinline__ unsigned s2u(const void* p) {
    return (unsigned)__cvta_generic_to_shared(p);
}
__device__ __forceinline__ void mbar_init(unsigned mbar, unsigned cnt) {
    asm volatile("mbarrier.init.shared.b64 [%0], %1;" :: "r"(mbar), "r"(cnt) : "memory");
}
__device__ __forceinline__ void mbar_expect_tx(unsigned mbar, unsigned bytes) {
    asm volatile("mbarrier.arrive.expect_tx.shared.b64 _, [%0], %1;"
                 :: "r"(mbar), "r"(bytes) : "memory");
}
__device__ __forceinline__ void bulk_g2s(unsigned dst_smem, const void* src, unsigned bytes,
                                         unsigned mbar) {
    asm volatile("cp.async.bulk.shared::cta.global.mbarrier::complete_tx::bytes "
                 "[%0], [%1], %2, [%3];"
                 :: "r"(dst_smem), "l"(src), "r"(bytes), "r"(mbar) : "memory");
}
__device__ __forceinline__ void mbar_wait(unsigned mbar, unsigned parity) {
    asm volatile(
        "{\n\t.reg .pred P;\n"
        "W%=:\n\t"
        "mbarrier.try_wait.parity.acquire.cta.shared::cta.b64 P, [%0], %1;\n\t"
        "@!P bra W%=;\n\t}"
        :: "r"(mbar), "r"(parity) : "memory");
}

// ---------------- Kernel A: fused input GEMVs (qkv, z, a, b) -----------------
// 194 blocks x 16 rows. Weights streamed via cp.async.bulk in 4 chunks;
// warp w waits chunk w/2 and computes rows 2w, 2w+1 of the block from smem.
__global__ __launch_bounds__(256) void gemv_in(
    const float* __restrict__ x,
    const float* __restrict__ Wqkv, const float* __restrict__ Wz,
    const float* __restrict__ Wa,   const float* __restrict__ Wb)
{
    extern __shared__ __align__(128) char smem[];
    float* sx = (float*)(smem + IN_SMEM_X);
    const float4* sw4 = (const float4*)(smem + IN_SMEM_W);
    const int tid  = threadIdx.x;
    const int lane = tid & 31;
    const int wid  = tid >> 5;
    const int b    = blockIdx.x;

    // block's contiguous weight source
    const float* wsrc;
    if (b < 128)       wsrc = Wqkv + (size_t)b * IN_RPB * H;
    else if (b < 192)  wsrc = Wz + (size_t)(b - 128) * IN_RPB * H;
    else if (b == 192) wsrc = Wa;
    else               wsrc = Wb;

    if (tid == 0) {
#pragma unroll
        for (int c = 0; c < 4; ++c) mbar_init(s2u(smem + IN_SMEM_MBAR) + c * 8, 1);
    }
    __syncthreads();
    if (tid == 0) {
#pragma unroll
        for (int c = 0; c < 4; ++c) {
            unsigned mb = s2u(smem + IN_SMEM_MBAR) + c * 8;
            mbar_expect_tx(mb, IN_CHUNKB);
            bulk_g2s(s2u(smem + IN_SMEM_W) + c * IN_CHUNKB,
                     (const char*)wsrc + c * IN_CHUNKB, IN_CHUNKB, mb);
        }
    }

    // stage x while weights stream
#pragma unroll
    for (int i = tid; i < H / 4; i += 256)
        ((float4*)sx)[i] = ((const float4*)x)[i];
    __syncthreads();

    // wait only this warp's chunk
    mbar_wait(s2u(smem + IN_SMEM_MBAR) + (wid >> 1) * 8, 0);

    const int r0 = 2 * wid;           // local rows r0, r0+1
    const float4* s4 = (const float4*)sx;
    float acc0 = 0.f, acc1 = 0.f;
#pragma unroll
    for (int j = 0; j < H / 128; ++j) {     // 12 iterations
        float4 xx = s4[j * 32 + lane];
        float4 a0 = sw4[(size_t)r0 * (H/4) + j * 32 + lane];
        float4 a1 = sw4[(size_t)(r0 + 1) * (H/4) + j * 32 + lane];
        acc0 += a0.x*xx.x + a0.y*xx.y + a0.z*xx.z + a0.w*xx.w;
        acc1 += a1.x*xx.x + a1.y*xx.y + a1.z*xx.z + a1.w*xx.w;
    }
    acc0 = warp_sum(acc0);
    acc1 = warp_sum(acc1);

    if (lane == 0) {
#pragma unroll
        for (int q = 0; q < 2; ++q) {
            int grow = b * IN_RPB + r0 + q;
            float v = q ? acc1 : acc0;
            if (grow < CONV_DIM)                        g_qkv[grow] = v;
            else if (grow < CONV_DIM + VALUE_DIM)       g_z[grow - CONV_DIM] = v;
            else if (grow < CONV_DIM + VALUE_DIM + HV)  g_ab[grow - CONV_DIM - VALUE_DIM] = v;
            else g_ab[HV + grow - CONV_DIM - VALUE_DIM - HV] = v;
        }
    }
}

// ------------- Kernel B: conv + l2norm + delta rule + gated RMSNorm ----------
__global__ __launch_bounds__(256) void delta_kernel(
    const float* __restrict__ convw, const float* __restrict__ Alog,
    const float* __restrict__ dtb,   const float* __restrict__ nw,
    const float* __restrict__ state, const float* __restrict__ cache)
{
    const int h   = blockIdx.x;       // value head 0..15
    const int kh  = h >> 1;
    const int tid = threadIdx.x;
    const int lane = tid & 31, wid = tid >> 5;

    __shared__ __align__(128) float sst[DK * DV];        // 16KB state tile
    __shared__ __align__(8) unsigned long long smbar;
    __shared__ float sq[DK], sk[DK], sv[DV];
    __shared__ float s_qs, s_ks, s_qk, s_eg, s_beta, s_rms;
    __shared__ float r_part[256], o_part[256];

    if (tid == 0) mbar_init(s2u(&smbar), 1);
    __syncthreads();
    if (tid == 0) {
        mbar_expect_tx(s2u(&smbar), DK * DV * 4);
        bulk_g2s(s2u(sst), state + (size_t)h * DK * DV, DK * DV * 4, s2u(&smbar));
    }

    // conv + SiLU for the 192 channels this head needs (overlaps state stream)
    if (tid < 192) {
        int ch;
        if (tid < 64)       ch = kh * 64 + tid;
        else if (tid < 128) ch = KEY_DIM + kh * 64 + (tid - 64);
        else                ch = 2 * KEY_DIM + h * 64 + (tid - 128);
        float co = g_qkv[ch]         * convw[ch * 4 + 3]
                 + cache[ch * 3 + 0] * convw[ch * 4 + 0]
                 + cache[ch * 3 + 1] * convw[ch * 4 + 1]
                 + cache[ch * 3 + 2] * convw[ch * 4 + 2];
        co = co / (1.f + expf(-co));  // silu
        if (tid < 64)       sq[tid] = co;
        else if (tid < 128) sk[tid - 64] = co;
        else                sv[tid - 128] = co;
    }
    __syncthreads();

    if (wid == 0) {
        float a = sq[lane], b2 = sq[lane + 32];
        float s = warp_sum(a * a + b2 * b2);
        if (lane == 0) s_qs = rsqrtf(s + 1e-12f) * 0.125f;  // * Dk^-0.5
    } else if (wid == 1) {
        float a = sk[lane], b2 = sk[lane + 32];
        float s = warp_sum(a * a + b2 * b2);
        if (lane == 0) s_ks = rsqrtf(s + 1e-12f);
    } else if (wid == 2) {
        float s = warp_sum(sq[lane] * sk[lane] + sq[lane + 32] * sk[lane + 32]);
        if (lane == 0) s_qk = s;
    } else if (wid == 3 && lane == 0) {
        float aa = g_ab[h] + dtb[h];
        float sp = (aa > 20.f) ? aa : log1pf(expf(aa));      // softplus
        s_eg = expf(-expf(Alog[h]) * sp);                    // exp(g)
        s_beta = 1.f / (1.f + expf(-g_ab[HV + h]));          // sigmoid
    }
    __syncthreads();

    const float qk = s_qk * s_qs * s_ks;

    if (tid < 64)       sq[tid]      *= s_qs;
    else if (tid < 128) sk[tid - 64] *= s_ks;
    __syncthreads();

    mbar_wait(s2u(&smbar), 0);    // state tile resident

    const int v  = tid & 63;
    const int kq = tid >> 6;
    float ar = 0.f, ao = 0.f;
#pragma unroll
    for (int kk = 0; kk < 16; ++kk) {
        int k = kq * 16 + kk;
        float s = sst[k * DV + v];
        ar += s * sk[k];
        ao += s * sq[k];
    }
    r_part[tid] = ar; o_part[tid] = ao;
    __syncthreads();

    if (tid < 64) {
        float r0 = r_part[v] + r_part[64 + v] + r_part[128 + v] + r_part[192 + v];
        float o0 = o_part[v] + o_part[64 + v] + o_part[128 + v] + o_part[192 + v];
        float delta = (sv[v] - s_eg * r0) * s_beta;
        float out   = s_eg * o0 + qk * delta;
        r_part[v] = out * out;
        o_part[v] = out;
    }
    __syncthreads();
    if (wid == 0) {
        float s = warp_sum(r_part[lane] + r_part[lane + 32]);
        if (lane == 0) s_rms = rsqrtf(s * (1.f / 64.f) + 1e-6f);
    }
    __syncthreads();
    if (tid < 64) {
        float zg  = g_z[h * 64 + v];
        float sil = zg / (1.f + expf(-zg));
        g_outf[h * 64 + v] = nw[v] * o_part[v] * s_rms * sil;
    }
}

// ---------------- Kernel C: y = W_out @ out_final ----------------------------
// 96 blocks x 16 rows, bulk-copied in 4 chunks; warp w computes rows 2w, 2w+1.
__global__ __launch_bounds__(256) void gemv_out(
    const float* __restrict__ Wout, float* __restrict__ y)
{
    extern __shared__ __align__(128) char smem[];
    float* so = (float*)(smem + OUT_SMEM_O);
    const float4* sw4 = (const float4*)(smem + OUT_SMEM_W);
    const int tid  = threadIdx.x;
    const int lane = tid & 31;
    const int wid  = tid >> 5;
    const int b    = blockIdx.x;

    if (tid == 0) {
#pragma unroll
        for (int c = 0; c < 4; ++c) mbar_init(s2u(smem + OUT_SMEM_MBAR) + c * 8, 1);
    }
    __syncthreads();
    if (tid == 0) {
        const float* wsrc = Wout + (size_t)b * OUT_RPB * VALUE_DIM;
#pragma unroll
        for (int c = 0; c < 4; ++c) {
            unsigned mb = s2u(smem + OUT_SMEM_MBAR) + c * 8;
            mbar_expect_tx(mb, OUT_CHUNKB);
            bulk_g2s(s2u(smem + OUT_SMEM_W) + c * OUT_CHUNKB,
                     (const char*)wsrc + c * OUT_CHUNKB, OUT_CHUNKB, mb);
        }
    }

#pragma unroll
    for (int i = tid; i < VALUE_DIM / 4; i += 256)
        ((float4*)so)[i] = ((const float4*)g_outf)[i];
    __syncthreads();

    mbar_wait(s2u(smem + OUT_SMEM_MBAR) + (wid >> 1) * 8, 0);

    const int r0 = 2 * wid;
    const float4* s4 = (const float4*)so;
    float acc0 = 0.f, acc1 = 0.f;
#pragma unroll
    for (int j = 0; j < VALUE_DIM / 128; ++j) {   // 8 iterations
        float4 xx = s4[j * 32 + lane];
        float4 a0 = sw4[(size_t)r0 * (VALUE_DIM/4) + j * 32 + lane];
        float4 a1 = sw4[(size_t)(r0 + 1) * (VALUE_DIM/4) + j * 32 + lane];
        acc0 += a0.x*xx.x + a0.y*xx.y + a0.z*xx.z + a0.w*xx.w;
        acc1 += a1.x*xx.x + a1.y*xx.y + a1.z*xx.z + a1.w*xx.w;
    }
    acc0 = warp_sum(acc0);
    acc1 = warp_sum(acc1);
    if (lane == 0) {
        y[b * OUT_RPB + r0]     = acc0;
        y[b * OUT_RPB + r0 + 1] = acc1;
    }
}

extern "C" void kernel_launch(void* const* d_in, const int* in_sizes, int n_in,
                              void* d_out, int out_size)
{
    const float* x     = (const float*)d_in[0];
    const float* Wqkv  = (const float*)d_in[1];
    const float* Wz    = (const float*)d_in[2];
    const float* Wa    = (const float*)d_in[3];
    const float* Wb    = (const float*)d_in[4];
    const float* Wout  = (const float*)d_in[5];
    const float* convw = (const float*)d_in[6];
    const float* Alog  = (const float*)d_in[7];
    const float* dtb   = (const float*)d_in[8];
    const float* nw    = (const float*)d_in[9];
    const float* state = (const float*)d_in[10];
    const float* cache = (const float*)d_in[11];
    float* y = (float*)d_out;

    cudaFuncSetAttribute(gemv_in,  cudaFuncAttributeMaxDynamicSharedMemorySize, IN_SMEM_TOTAL);
    cudaFuncSetAttribute(gemv_out, cudaFuncAttributeMaxDynamicSharedMemorySize, OUT_SMEM_TOTAL);

    gemv_in<<<IN_BLOCKS, 256, IN_SMEM_TOTAL>>>(x, Wqkv, Wz, Wa, Wb);
    delta_kernel<<<HV, 256>>>(convw, Alog, dtb, nw, state, cache);
    gemv_out<<<OUT_BLOCKS, 256, OUT_SMEM_TOTAL>>>(Wout, y);
}